// round 7
// baseline (speedup 1.0000x reference)
#include <cuda_runtime.h>
#include <cuda_bf16.h>
#include <cstdint>

// Problem constants (fixed by the dataset generator).
#define NNODES 100000
#define NEDGES 1600000
#define F_IN   128
#define HID    64
#define HID4   (HID / 4)          // float4s per node row = 16

// Scratch (static __device__ globals -- no allocation allowed).
// Feature buffers are float4-typed => guaranteed 16B alignment for v4 ld/st.
__device__ float  g_deg [NNODES];
__device__ float  g_dinv[NNODES];
__device__ float4 g_bufA[(size_t)NNODES * HID4];   // hs = (x@W)*dinv (gather src)
__device__ float4 g_bufB[(size_t)NNODES * HID4];   // aggregation accumulator
__device__ int2   g_edges[NEDGES];                 // (src,dst) as int32

// ---------------------------------------------------------------------------
// K0: deg init (self-loop contributes 1)
// ---------------------------------------------------------------------------
__global__ void k_init_deg() {
    int v = blockIdx.x * blockDim.x + threadIdx.x;
    if (v < NNODES) g_deg[v] = 1.0f;
}

// K1: count in-degrees + pack edge index into int2
// NOTE: edge_index is int32 on device (JAX default x64-disabled coerces
// jnp.int64 -> int32). Reading as int64 was the R6 OOB fault.
__global__ void k_deg(const int* __restrict__ ei) {
    int e = blockIdx.x * blockDim.x + threadIdx.x;
    if (e < NEDGES) {
        int s = ei[e];
        int d = ei[NEDGES + e];
        g_edges[e] = make_int2(s, d);
        atomicAdd(&g_deg[d], 1.0f);
    }
}

// K2: dinv = rsqrt(deg)
__global__ void k_dinv() {
    int v = blockIdx.x * blockDim.x + threadIdx.x;
    if (v < NNODES) g_dinv[v] = rsqrtf(g_deg[v]);
}

// ---------------------------------------------------------------------------
// K3: GEMM1  bufA = bufB = (x @ W1) * dinv[row]
//   block tile: 128 rows x 64 cols, 256 threads, thread tile 8 rows x 4 cols
//   K=128 in four chunks of 32.  smem: 18432 + 8192 = 26624 B (< 48 KB).
// ---------------------------------------------------------------------------
__global__ __launch_bounds__(256) void k_gemm1(const float* __restrict__ x,
                                               const float* __restrict__ W1) {
    __shared__ float sX[128][36];   // stride 36 floats = 144 B (16B aligned)
    __shared__ float sW[32][64];

    const int m0  = blockIdx.x * 128;
    const int tid = threadIdx.x;
    const int tx  = tid & 15;       // col group: cols tx*4 .. tx*4+3
    const int ty  = tid >> 4;       // row lane : rows ty, ty+16, ..., ty+112

    float4 acc[8];
#pragma unroll
    for (int i = 0; i < 8; i++) acc[i] = make_float4(0.f, 0.f, 0.f, 0.f);

#pragma unroll
    for (int kc = 0; kc < 4; kc++) {
        // stage X chunk: 128 rows x 32 cols = 1024 float4
#pragma unroll
        for (int l = 0; l < 4; l++) {
            int idx = tid + l * 256;          // 0..1023
            int r = idx >> 3, c4 = idx & 7;
            int row = m0 + r;
            float4 v = make_float4(0.f, 0.f, 0.f, 0.f);
            if (row < NNODES)
                v = __ldg((const float4*)(x + (size_t)row * F_IN + kc * 32) + c4);
            *(float4*)&sX[r][c4 * 4] = v;
        }
        // stage W chunk: 32 x 64 = 512 float4
#pragma unroll
        for (int l = 0; l < 2; l++) {
            int idx = tid + l * 256;          // 0..511
            int k = idx >> 4, c4 = idx & 15;
            *(float4*)&sW[k][c4 * 4] =
                __ldg((const float4*)(W1 + (size_t)(kc * 32 + k) * HID) + c4);
        }
        __syncthreads();

#pragma unroll
        for (int k = 0; k < 32; k++) {
            float4 w = *(const float4*)&sW[k][tx * 4];
#pragma unroll
            for (int i = 0; i < 8; i++) {
                float h = sX[ty + i * 16][k];
                acc[i].x = fmaf(h, w.x, acc[i].x);
                acc[i].y = fmaf(h, w.y, acc[i].y);
                acc[i].z = fmaf(h, w.z, acc[i].z);
                acc[i].w = fmaf(h, w.w, acc[i].w);
            }
        }
        __syncthreads();
    }

#pragma unroll
    for (int i = 0; i < 8; i++) {
        int row = m0 + ty + i * 16;
        if (row < NNODES) {
            float dv = g_dinv[row];
            float4 v = acc[i];
            v.x *= dv; v.y *= dv; v.z *= dv; v.w *= dv;
            g_bufA[(size_t)row * HID4 + tx] = v;
            g_bufB[(size_t)row * HID4 + tx] = v;   // self-loop init
        }
    }
}

// ---------------------------------------------------------------------------
// K4: scatter-aggregate: for each edge, bufB[dst] += bufA[src]
//   16 threads per edge, float4 gather, 4 scalar reds per thread.
// ---------------------------------------------------------------------------
__global__ __launch_bounds__(256) void k_scatter() {
    int gid = blockIdx.x * 256 + threadIdx.x;
    int e = gid >> 4;
    int q = gid & 15;
    if (e < NEDGES) {
        int2 ed = g_edges[e];
        float4 v = __ldg(g_bufA + (size_t)ed.x * HID4 + q);
        float* dst = (float*)(g_bufB + (size_t)ed.y * HID4 + q);
        atomicAdd(dst + 0, v.x);
        atomicAdd(dst + 1, v.y);
        atomicAdd(dst + 2, v.z);
        atomicAdd(dst + 3, v.w);
    }
}

// ---------------------------------------------------------------------------
// K5: layer-1 finish + GEMM2 fused:
//   h1 = relu(bufB*dinv + b1)  (in smem staging, per 32-col chunk)
//   bufA = bufB = (h1 @ W2) * dinv
// ---------------------------------------------------------------------------
__global__ __launch_bounds__(256) void k_layer2(const float* __restrict__ W2,
                                                const float* __restrict__ b1) {
    __shared__ float sX[128][36];
    __shared__ float sW[32][64];

    const int m0  = blockIdx.x * 128;
    const int tid = threadIdx.x;
    const int tx  = tid & 15;
    const int ty  = tid >> 4;

    float4 acc[8];
#pragma unroll
    for (int i = 0; i < 8; i++) acc[i] = make_float4(0.f, 0.f, 0.f, 0.f);

#pragma unroll
    for (int kc = 0; kc < 2; kc++) {
        // stage h1 chunk with fused relu/bias/norm: 128 rows x 32 cols
#pragma unroll
        for (int l = 0; l < 4; l++) {
            int idx = tid + l * 256;
            int r = idx >> 3, c4 = idx & 7;
            int row = m0 + r;
            float4 v = make_float4(0.f, 0.f, 0.f, 0.f);
            if (row < NNODES) {
                v = g_bufB[(size_t)row * HID4 + kc * 8 + c4];
                float dv = g_dinv[row];
                float4 bb = __ldg((const float4*)b1 + kc * 8 + c4);
                v.x = fmaxf(fmaf(v.x, dv, bb.x), 0.f);
                v.y = fmaxf(fmaf(v.y, dv, bb.y), 0.f);
                v.z = fmaxf(fmaf(v.z, dv, bb.z), 0.f);
                v.w = fmaxf(fmaf(v.w, dv, bb.w), 0.f);
            }
            *(float4*)&sX[r][c4 * 4] = v;
        }
        // stage W2 chunk: 32 x 64
#pragma unroll
        for (int l = 0; l < 2; l++) {
            int idx = tid + l * 256;
            int k = idx >> 4, c4 = idx & 15;
            *(float4*)&sW[k][c4 * 4] =
                __ldg((const float4*)(W2 + (size_t)(kc * 32 + k) * HID) + c4);
        }
        __syncthreads();

#pragma unroll
        for (int k = 0; k < 32; k++) {
            float4 w = *(const float4*)&sW[k][tx * 4];
#pragma unroll
            for (int i = 0; i < 8; i++) {
                float h = sX[ty + i * 16][k];
                acc[i].x = fmaf(h, w.x, acc[i].x);
                acc[i].y = fmaf(h, w.y, acc[i].y);
                acc[i].z = fmaf(h, w.z, acc[i].z);
                acc[i].w = fmaf(h, w.w, acc[i].w);
            }
        }
        __syncthreads();
    }

    // safe to overwrite bufB: all reads of this block's rows happened pre-sync,
    // and no other block touches these rows.
#pragma unroll
    for (int i = 0; i < 8; i++) {
        int row = m0 + ty + i * 16;
        if (row < NNODES) {
            float dv = g_dinv[row];
            float4 v = acc[i];
            v.x *= dv; v.y *= dv; v.z *= dv; v.w *= dv;
            g_bufA[(size_t)row * HID4 + tx] = v;
            g_bufB[(size_t)row * HID4 + tx] = v;   // self-loop init
        }
    }
}

// ---------------------------------------------------------------------------
// K6: head:  out[v] = relu(bufB[v]*dinv + b2) . Wd + bd   (warp per node)
//   Each lane handles 2 consecutive features (float2), 32 lanes cover 64.
// ---------------------------------------------------------------------------
__global__ __launch_bounds__(256) void k_final(const float* __restrict__ Wd,
                                               const float* __restrict__ b2,
                                               const float* __restrict__ bd,
                                               float* __restrict__ out) {
    int warp = (blockIdx.x * 256 + threadIdx.x) >> 5;
    int lane = threadIdx.x & 31;
    if (warp >= NNODES) return;
    float  dv = g_dinv[warp];
    float2 v  = *((const float2*)(g_bufB + (size_t)warp * HID4) + lane);
    float2 b  = __ldg((const float2*)b2 + lane);
    float2 w  = __ldg((const float2*)Wd + lane);
    float s = fmaxf(fmaf(v.x, dv, b.x), 0.f) * w.x
            + fmaxf(fmaf(v.y, dv, b.y), 0.f) * w.y;
#pragma unroll
    for (int o = 16; o > 0; o >>= 1)
        s += __shfl_down_sync(0xffffffffu, s, o);
    if (lane == 0) out[warp] = s + __ldg(bd);
}

// ---------------------------------------------------------------------------
extern "C" void kernel_launch(void* const* d_in, const int* in_sizes, int n_in,
                              void* d_out, int out_size) {
    const float* x   = (const float*)d_in[0];
    const int*   ei  = (const int*)d_in[1];     // int32! (JAX x64 disabled)
    const float* W1  = (const float*)d_in[2];
    const float* b1  = (const float*)d_in[3];
    const float* W2  = (const float*)d_in[4];
    const float* b2  = (const float*)d_in[5];
    const float* Wd  = (const float*)d_in[6];
    const float* bd  = (const float*)d_in[7];
    float*       out = (float*)d_out;

    k_init_deg<<<(NNODES + 255) / 256, 256>>>();
    k_deg     <<<(NEDGES + 255) / 256, 256>>>(ei);
    k_dinv    <<<(NNODES + 255) / 256, 256>>>();

    k_gemm1   <<<(NNODES + 127) / 128, 256>>>(x, W1);
    k_scatter <<<(NEDGES * 16) / 256, 256>>>();          // = 100000 blocks exactly

    k_layer2  <<<(NNODES + 127) / 128, 256>>>(W2, b1);
    k_scatter <<<(NEDGES * 16) / 256, 256>>>();

    k_final   <<<(NNODES * 32 + 255) / 256, 256>>>(Wd, b2, bd, out);
}

// round 8
// speedup vs baseline: 2.8053x; 2.8053x over previous
#include <cuda_runtime.h>
#include <cuda_bf16.h>
#include <cstdint>

// Problem constants (fixed by the dataset generator).
#define NNODES 100000
#define NEDGES 1600000
#define F_IN   128
#define HID    64
#define HID4   (HID / 4)          // float4s per node row = 16

#define SCAN_T 1024
#define NSCANB ((NNODES + SCAN_T - 1) / SCAN_T)   // 98

// Scratch (static __device__ globals -- no allocation allowed).
__device__ float  g_dinv[NNODES];
__device__ float4 g_bufA[(size_t)NNODES * HID4];   // GEMM output, gather source
__device__ float4 g_bufB[(size_t)NNODES * HID4];   // aggregated sums
__device__ int    g_degi  [NNODES];
__device__ int    g_cursor[NNODES];
__device__ int    g_rowptr[NNODES + 1];
__device__ int    g_bsum  [NSCANB];
__device__ int    g_csrc  [NEDGES];                // CSR: src ids bucketed by dst

// ---------------------------------------------------------------------------
// CSR construction
// ---------------------------------------------------------------------------
__global__ void k_zero() {
    int v = blockIdx.x * blockDim.x + threadIdx.x;
    if (v < NNODES) { g_degi[v] = 0; g_cursor[v] = 0; }
}

__global__ void k_count(const int* __restrict__ ei) {
    int e = blockIdx.x * blockDim.x + threadIdx.x;
    if (e < NEDGES) atomicAdd(&g_degi[ei[NEDGES + e]], 1);
}

// 3-phase exclusive scan of g_degi -> g_rowptr
__global__ __launch_bounds__(SCAN_T) void k_scan1() {
    __shared__ int s[SCAN_T];
    int i = blockIdx.x * SCAN_T + threadIdx.x;
    int v = (i < NNODES) ? g_degi[i] : 0;
    s[threadIdx.x] = v;
    __syncthreads();
    for (int off = 1; off < SCAN_T; off <<= 1) {
        int t = (threadIdx.x >= off) ? s[threadIdx.x - off] : 0;
        __syncthreads();
        s[threadIdx.x] += t;
        __syncthreads();
    }
    if (i < NNODES) g_rowptr[i] = s[threadIdx.x] - v;       // block-local exclusive
    if (threadIdx.x == SCAN_T - 1) g_bsum[blockIdx.x] = s[SCAN_T - 1];
}

__global__ __launch_bounds__(SCAN_T) void k_scan2() {
    __shared__ int s[SCAN_T];
    int v = (threadIdx.x < NSCANB) ? g_bsum[threadIdx.x] : 0;
    s[threadIdx.x] = v;
    __syncthreads();
    for (int off = 1; off < SCAN_T; off <<= 1) {
        int t = (threadIdx.x >= off) ? s[threadIdx.x - off] : 0;
        __syncthreads();
        s[threadIdx.x] += t;
        __syncthreads();
    }
    if (threadIdx.x < NSCANB) g_bsum[threadIdx.x] = s[threadIdx.x] - v;  // exclusive
    if (threadIdx.x == 0) g_rowptr[NNODES] = NEDGES;
}

__global__ __launch_bounds__(SCAN_T) void k_scan3() {
    int i = blockIdx.x * SCAN_T + threadIdx.x;
    if (i < NNODES) g_rowptr[i] += g_bsum[blockIdx.x];
}

// place each edge's src into its dst bucket
__global__ void k_fill(const int* __restrict__ ei) {
    int e = blockIdx.x * blockDim.x + threadIdx.x;
    if (e < NEDGES) {
        int s = ei[e];
        int d = ei[NEDGES + e];
        int pos = g_rowptr[d] + atomicAdd(&g_cursor[d], 1);
        g_csrc[pos] = s;
    }
}

// dinv = rsqrt(in-degree + 1 self-loop)
__global__ void k_dinv() {
    int v = blockIdx.x * blockDim.x + threadIdx.x;
    if (v < NNODES) g_dinv[v] = rsqrtf((float)(g_degi[v] + 1));
}

// ---------------------------------------------------------------------------
// K3: GEMM1  bufA = (x @ W1) * dinv[row]
// ---------------------------------------------------------------------------
__global__ __launch_bounds__(256) void k_gemm1(const float* __restrict__ x,
                                               const float* __restrict__ W1) {
    __shared__ float sX[128][36];   // stride 144 B (16B aligned)
    __shared__ float sW[32][64];

    const int m0  = blockIdx.x * 128;
    const int tid = threadIdx.x;
    const int tx  = tid & 15;
    const int ty  = tid >> 4;

    float4 acc[8];
#pragma unroll
    for (int i = 0; i < 8; i++) acc[i] = make_float4(0.f, 0.f, 0.f, 0.f);

#pragma unroll
    for (int kc = 0; kc < 4; kc++) {
#pragma unroll
        for (int l = 0; l < 4; l++) {
            int idx = tid + l * 256;
            int r = idx >> 3, c4 = idx & 7;
            int row = m0 + r;
            float4 v = make_float4(0.f, 0.f, 0.f, 0.f);
            if (row < NNODES)
                v = __ldg((const float4*)(x + (size_t)row * F_IN + kc * 32) + c4);
            *(float4*)&sX[r][c4 * 4] = v;
        }
#pragma unroll
        for (int l = 0; l < 2; l++) {
            int idx = tid + l * 256;
            int k = idx >> 4, c4 = idx & 15;
            *(float4*)&sW[k][c4 * 4] =
                __ldg((const float4*)(W1 + (size_t)(kc * 32 + k) * HID) + c4);
        }
        __syncthreads();

#pragma unroll
        for (int k = 0; k < 32; k++) {
            float4 w = *(const float4*)&sW[k][tx * 4];
#pragma unroll
            for (int i = 0; i < 8; i++) {
                float h = sX[ty + i * 16][k];
                acc[i].x = fmaf(h, w.x, acc[i].x);
                acc[i].y = fmaf(h, w.y, acc[i].y);
                acc[i].z = fmaf(h, w.z, acc[i].z);
                acc[i].w = fmaf(h, w.w, acc[i].w);
            }
        }
        __syncthreads();
    }

#pragma unroll
    for (int i = 0; i < 8; i++) {
        int row = m0 + ty + i * 16;
        if (row < NNODES) {
            float dv = g_dinv[row];
            float4 v = acc[i];
            v.x *= dv; v.y *= dv; v.z *= dv; v.w *= dv;
            g_bufA[(size_t)row * HID4 + tx] = v;
        }
    }
}

// ---------------------------------------------------------------------------
// K4: CSR aggregation: bufB[v] = bufA[v] + sum_{s in N_in(v)} bufA[s]
//   16 threads per node; register accumulation; single store; NO atomics.
// ---------------------------------------------------------------------------
__global__ __launch_bounds__(256) void k_aggr() {
    int gid = blockIdx.x * 256 + threadIdx.x;
    int v = gid >> 4;
    int q = gid & 15;
    if (v >= NNODES) return;

    float4 acc = g_bufA[(size_t)v * HID4 + q];     // self-loop term
    int beg = g_rowptr[v];
    int end = g_rowptr[v + 1];

    int i = beg;
    // 2-way unroll for a little MLP on the dependent gathers
    for (; i + 2 <= end; i += 2) {
        int s0 = g_csrc[i];
        int s1 = g_csrc[i + 1];
        float4 t0 = __ldg(g_bufA + (size_t)s0 * HID4 + q);
        float4 t1 = __ldg(g_bufA + (size_t)s1 * HID4 + q);
        acc.x += t0.x + t1.x;
        acc.y += t0.y + t1.y;
        acc.z += t0.z + t1.z;
        acc.w += t0.w + t1.w;
    }
    if (i < end) {
        int s0 = g_csrc[i];
        float4 t0 = __ldg(g_bufA + (size_t)s0 * HID4 + q);
        acc.x += t0.x; acc.y += t0.y; acc.z += t0.z; acc.w += t0.w;
    }
    g_bufB[(size_t)v * HID4 + q] = acc;
}

// ---------------------------------------------------------------------------
// K5: layer-1 finish + GEMM2 fused:
//   h1 = relu(bufB*dinv + b1)  (smem staging);  bufA = (h1 @ W2) * dinv
// ---------------------------------------------------------------------------
__global__ __launch_bounds__(256) void k_layer2(const float* __restrict__ W2,
                                                const float* __restrict__ b1) {
    __shared__ float sX[128][36];
    __shared__ float sW[32][64];

    const int m0  = blockIdx.x * 128;
    const int tid = threadIdx.x;
    const int tx  = tid & 15;
    const int ty  = tid >> 4;

    float4 acc[8];
#pragma unroll
    for (int i = 0; i < 8; i++) acc[i] = make_float4(0.f, 0.f, 0.f, 0.f);

#pragma unroll
    for (int kc = 0; kc < 2; kc++) {
#pragma unroll
        for (int l = 0; l < 4; l++) {
            int idx = tid + l * 256;
            int r = idx >> 3, c4 = idx & 7;
            int row = m0 + r;
            float4 v = make_float4(0.f, 0.f, 0.f, 0.f);
            if (row < NNODES) {
                v = g_bufB[(size_t)row * HID4 + kc * 8 + c4];
                float dv = g_dinv[row];
                float4 bb = __ldg((const float4*)b1 + kc * 8 + c4);
                v.x = fmaxf(fmaf(v.x, dv, bb.x), 0.f);
                v.y = fmaxf(fmaf(v.y, dv, bb.y), 0.f);
                v.z = fmaxf(fmaf(v.z, dv, bb.z), 0.f);
                v.w = fmaxf(fmaf(v.w, dv, bb.w), 0.f);
            }
            *(float4*)&sX[r][c4 * 4] = v;
        }
#pragma unroll
        for (int l = 0; l < 2; l++) {
            int idx = tid + l * 256;
            int k = idx >> 4, c4 = idx & 15;
            *(float4*)&sW[k][c4 * 4] =
                __ldg((const float4*)(W2 + (size_t)(kc * 32 + k) * HID) + c4);
        }
        __syncthreads();

#pragma unroll
        for (int k = 0; k < 32; k++) {
            float4 w = *(const float4*)&sW[k][tx * 4];
#pragma unroll
            for (int i = 0; i < 8; i++) {
                float h = sX[ty + i * 16][k];
                acc[i].x = fmaf(h, w.x, acc[i].x);
                acc[i].y = fmaf(h, w.y, acc[i].y);
                acc[i].z = fmaf(h, w.z, acc[i].z);
                acc[i].w = fmaf(h, w.w, acc[i].w);
            }
        }
        __syncthreads();
    }

#pragma unroll
    for (int i = 0; i < 8; i++) {
        int row = m0 + ty + i * 16;
        if (row < NNODES) {
            float dv = g_dinv[row];
            float4 v = acc[i];
            v.x *= dv; v.y *= dv; v.z *= dv; v.w *= dv;
            g_bufA[(size_t)row * HID4 + tx] = v;
        }
    }
}

// ---------------------------------------------------------------------------
// K6: head:  out[v] = relu(bufB[v]*dinv + b2) . Wd + bd   (warp per node)
// ---------------------------------------------------------------------------
__global__ __launch_bounds__(256) void k_final(const float* __restrict__ Wd,
                                               const float* __restrict__ b2,
                                               const float* __restrict__ bd,
                                               float* __restrict__ out) {
    int warp = (blockIdx.x * 256 + threadIdx.x) >> 5;
    int lane = threadIdx.x & 31;
    if (warp >= NNODES) return;
    float  dv = g_dinv[warp];
    float2 v  = *((const float2*)(g_bufB + (size_t)warp * HID4) + lane);
    float2 b  = __ldg((const float2*)b2 + lane);
    float2 w  = __ldg((const float2*)Wd + lane);
    float s = fmaxf(fmaf(v.x, dv, b.x), 0.f) * w.x
            + fmaxf(fmaf(v.y, dv, b.y), 0.f) * w.y;
#pragma unroll
    for (int o = 16; o > 0; o >>= 1)
        s += __shfl_down_sync(0xffffffffu, s, o);
    if (lane == 0) out[warp] = s + __ldg(bd);
}

// ---------------------------------------------------------------------------
extern "C" void kernel_launch(void* const* d_in, const int* in_sizes, int n_in,
                              void* d_out, int out_size) {
    const float* x   = (const float*)d_in[0];
    const int*   ei  = (const int*)d_in[1];     // int32 (JAX x64 disabled)
    const float* W1  = (const float*)d_in[2];
    const float* b1  = (const float*)d_in[3];
    const float* W2  = (const float*)d_in[4];
    const float* b2  = (const float*)d_in[5];
    const float* Wd  = (const float*)d_in[6];
    const float* bd  = (const float*)d_in[7];
    float*       out = (float*)d_out;

    // CSR build (once, reused by both layers)
    k_zero <<<(NNODES + 255) / 256, 256>>>();
    k_count<<<(NEDGES + 255) / 256, 256>>>(ei);
    k_scan1<<<NSCANB, SCAN_T>>>();
    k_scan2<<<1, SCAN_T>>>();
    k_scan3<<<NSCANB, SCAN_T>>>();
    k_fill <<<(NEDGES + 255) / 256, 256>>>(ei);
    k_dinv <<<(NNODES + 255) / 256, 256>>>();

    // layer 1
    k_gemm1<<<(NNODES + 127) / 128, 256>>>(x, W1);
    k_aggr <<<(NNODES * 16 + 255) / 256, 256>>>();

    // layer 2
    k_layer2<<<(NNODES + 127) / 128, 256>>>(W2, b1);
    k_aggr  <<<(NNODES * 16 + 255) / 256, 256>>>();

    // head
    k_final<<<(NNODES * 32 + 255) / 256, 256>>>(Wd, b2, bd, out);
}

// round 9
// speedup vs baseline: 2.8711x; 1.0234x over previous
#include <cuda_runtime.h>
#include <cuda_bf16.h>
#include <cstdint>

// Problem constants (fixed by the dataset generator).
#define NNODES 100000
#define NEDGES 1600000
#define F_IN   128
#define HID    64
#define HID4   (HID / 4)          // float4s per node row = 16

#define SCAN_T 1024
#define NSCANB ((NNODES + SCAN_T - 1) / SCAN_T)   // 98

// Scratch (static __device__ globals -- no allocation allowed).
__device__ float  g_dinv[NNODES];
__device__ float4 g_bufA[(size_t)NNODES * HID4];   // GEMM output, gather source
__device__ float4 g_bufB[(size_t)NNODES * HID4];   // aggregated sums
__device__ int    g_degi  [NNODES];
__device__ int    g_cursor[NNODES];
__device__ int    g_rowptr[NNODES + 1];
__device__ int    g_bsum  [NSCANB];
__device__ int    g_csrc  [NEDGES];                // CSR: src ids bucketed by dst

// ---------------------------------------------------------------------------
// Packed fp32x2 helpers (Blackwell FFMA2: 2x fp32 FMA throughput, exact fp32)
// ---------------------------------------------------------------------------
__device__ __forceinline__ unsigned long long pack2(float a, float b) {
    unsigned long long r;
    asm("mov.b64 %0, {%1, %2};" : "=l"(r) : "f"(a), "f"(b));
    return r;
}
__device__ __forceinline__ void ffma2(unsigned long long& c,
                                      unsigned long long a,
                                      unsigned long long b) {
    asm("fma.rn.f32x2 %0, %1, %2, %0;" : "+l"(c) : "l"(a), "l"(b));
}
__device__ __forceinline__ float2 unpack2(unsigned long long v) {
    float2 f;
    asm("mov.b64 {%0, %1}, %2;" : "=f"(f.x), "=f"(f.y) : "l"(v));
    return f;
}

// ---------------------------------------------------------------------------
// CSR construction
// ---------------------------------------------------------------------------
__global__ void k_zero() {
    int v = blockIdx.x * blockDim.x + threadIdx.x;
    if (v < NNODES) { g_degi[v] = 0; g_cursor[v] = 0; }
}

__global__ void k_count(const int* __restrict__ ei) {
    int e = blockIdx.x * blockDim.x + threadIdx.x;
    if (e < NEDGES) atomicAdd(&g_degi[ei[NEDGES + e]], 1);
}

// 3-phase exclusive scan of g_degi -> g_rowptr
__global__ __launch_bounds__(SCAN_T) void k_scan1() {
    __shared__ int s[SCAN_T];
    int i = blockIdx.x * SCAN_T + threadIdx.x;
    int v = (i < NNODES) ? g_degi[i] : 0;
    s[threadIdx.x] = v;
    __syncthreads();
    for (int off = 1; off < SCAN_T; off <<= 1) {
        int t = (threadIdx.x >= off) ? s[threadIdx.x - off] : 0;
        __syncthreads();
        s[threadIdx.x] += t;
        __syncthreads();
    }
    if (i < NNODES) g_rowptr[i] = s[threadIdx.x] - v;       // block-local exclusive
    if (threadIdx.x == SCAN_T - 1) g_bsum[blockIdx.x] = s[SCAN_T - 1];
}

__global__ __launch_bounds__(SCAN_T) void k_scan2() {
    __shared__ int s[SCAN_T];
    int v = (threadIdx.x < NSCANB) ? g_bsum[threadIdx.x] : 0;
    s[threadIdx.x] = v;
    __syncthreads();
    for (int off = 1; off < SCAN_T; off <<= 1) {
        int t = (threadIdx.x >= off) ? s[threadIdx.x - off] : 0;
        __syncthreads();
        s[threadIdx.x] += t;
        __syncthreads();
    }
    if (threadIdx.x < NSCANB) g_bsum[threadIdx.x] = s[threadIdx.x] - v;  // exclusive
    if (threadIdx.x == 0) g_rowptr[NNODES] = NEDGES;
}

// scan finish + dinv fused (one less launch)
__global__ __launch_bounds__(SCAN_T) void k_scan3() {
    int i = blockIdx.x * SCAN_T + threadIdx.x;
    if (i < NNODES) {
        g_rowptr[i] += g_bsum[blockIdx.x];
        g_dinv[i] = rsqrtf((float)(g_degi[i] + 1));
    }
}

// place each edge's src into its dst bucket
__global__ void k_fill(const int* __restrict__ ei) {
    int e = blockIdx.x * blockDim.x + threadIdx.x;
    if (e < NEDGES) {
        int s = ei[e];
        int d = ei[NEDGES + e];
        int pos = g_rowptr[d] + atomicAdd(&g_cursor[d], 1);
        g_csrc[pos] = s;
    }
}

// ---------------------------------------------------------------------------
// K3: GEMM1  bufA = (x @ W1) * dinv[row]   -- f32x2 packed FMA inner loop
// ---------------------------------------------------------------------------
__global__ __launch_bounds__(256) void k_gemm1(const float* __restrict__ x,
                                               const float* __restrict__ W1) {
    __shared__ float sX[128][36];   // stride 144 B (16B aligned)
    __shared__ float sW[32][64];

    const int m0  = blockIdx.x * 128;
    const int tid = threadIdx.x;
    const int tx  = tid & 15;
    const int ty  = tid >> 4;

    unsigned long long axy[8], azw[8];
    const unsigned long long z2 = pack2(0.f, 0.f);
#pragma unroll
    for (int i = 0; i < 8; i++) { axy[i] = z2; azw[i] = z2; }

#pragma unroll
    for (int kc = 0; kc < 4; kc++) {
#pragma unroll
        for (int l = 0; l < 4; l++) {
            int idx = tid + l * 256;
            int r = idx >> 3, c4 = idx & 7;
            int row = m0 + r;
            float4 v = make_float4(0.f, 0.f, 0.f, 0.f);
            if (row < NNODES)
                v = __ldg((const float4*)(x + (size_t)row * F_IN + kc * 32) + c4);
            *(float4*)&sX[r][c4 * 4] = v;
        }
#pragma unroll
        for (int l = 0; l < 2; l++) {
            int idx = tid + l * 256;
            int k = idx >> 4, c4 = idx & 15;
            *(float4*)&sW[k][c4 * 4] =
                __ldg((const float4*)(W1 + (size_t)(kc * 32 + k) * HID) + c4);
        }
        __syncthreads();

#pragma unroll
        for (int k = 0; k < 32; k++) {
            float4 w = *(const float4*)&sW[k][tx * 4];
            unsigned long long wxy = pack2(w.x, w.y);
            unsigned long long wzw = pack2(w.z, w.w);
#pragma unroll
            for (int i = 0; i < 8; i++) {
                float h = sX[ty + i * 16][k];
                unsigned long long hh = pack2(h, h);
                ffma2(axy[i], hh, wxy);
                ffma2(azw[i], hh, wzw);
            }
        }
        __syncthreads();
    }

#pragma unroll
    for (int i = 0; i < 8; i++) {
        int row = m0 + ty + i * 16;
        if (row < NNODES) {
            float dv = g_dinv[row];
            float2 pxy = unpack2(axy[i]);
            float2 pzw = unpack2(azw[i]);
            float4 v = make_float4(pxy.x * dv, pxy.y * dv, pzw.x * dv, pzw.y * dv);
            g_bufA[(size_t)row * HID4 + tx] = v;
        }
    }
}

// ---------------------------------------------------------------------------
// K4: CSR aggregation: bufB[v] = bufA[v] + sum_{s in N_in(v)} bufA[s]
//   16 threads per node; register accumulation; single store; NO atomics.
// ---------------------------------------------------------------------------
__global__ __launch_bounds__(256) void k_aggr() {
    int gid = blockIdx.x * 256 + threadIdx.x;
    int v = gid >> 4;
    int q = gid & 15;
    if (v >= NNODES) return;

    float4 acc = g_bufA[(size_t)v * HID4 + q];     // self-loop term
    int beg = g_rowptr[v];
    int end = g_rowptr[v + 1];

    int i = beg;
    for (; i + 2 <= end; i += 2) {
        int s0 = g_csrc[i];
        int s1 = g_csrc[i + 1];
        float4 t0 = __ldg(g_bufA + (size_t)s0 * HID4 + q);
        float4 t1 = __ldg(g_bufA + (size_t)s1 * HID4 + q);
        acc.x += t0.x + t1.x;
        acc.y += t0.y + t1.y;
        acc.z += t0.z + t1.z;
        acc.w += t0.w + t1.w;
    }
    if (i < end) {
        int s0 = g_csrc[i];
        float4 t0 = __ldg(g_bufA + (size_t)s0 * HID4 + q);
        acc.x += t0.x; acc.y += t0.y; acc.z += t0.z; acc.w += t0.w;
    }
    g_bufB[(size_t)v * HID4 + q] = acc;
}

// ---------------------------------------------------------------------------
// K5: layer-1 finish + GEMM2 fused (f32x2 inner loop):
//   h1 = relu(bufB*dinv + b1)  (smem staging);  bufA = (h1 @ W2) * dinv
// ---------------------------------------------------------------------------
__global__ __launch_bounds__(256) void k_layer2(const float* __restrict__ W2,
                                                const float* __restrict__ b1) {
    __shared__ float sX[128][36];
    __shared__ float sW[32][64];

    const int m0  = blockIdx.x * 128;
    const int tid = threadIdx.x;
    const int tx  = tid & 15;
    const int ty  = tid >> 4;

    unsigned long long axy[8], azw[8];
    const unsigned long long z2 = pack2(0.f, 0.f);
#pragma unroll
    for (int i = 0; i < 8; i++) { axy[i] = z2; azw[i] = z2; }

#pragma unroll
    for (int kc = 0; kc < 2; kc++) {
#pragma unroll
        for (int l = 0; l < 4; l++) {
            int idx = tid + l * 256;
            int r = idx >> 3, c4 = idx & 7;
            int row = m0 + r;
            float4 v = make_float4(0.f, 0.f, 0.f, 0.f);
            if (row < NNODES) {
                v = g_bufB[(size_t)row * HID4 + kc * 8 + c4];
                float dv = g_dinv[row];
                float4 bb = __ldg((const float4*)b1 + kc * 8 + c4);
                v.x = fmaxf(fmaf(v.x, dv, bb.x), 0.f);
                v.y = fmaxf(fmaf(v.y, dv, bb.y), 0.f);
                v.z = fmaxf(fmaf(v.z, dv, bb.z), 0.f);
                v.w = fmaxf(fmaf(v.w, dv, bb.w), 0.f);
            }
            *(float4*)&sX[r][c4 * 4] = v;
        }
#pragma unroll
        for (int l = 0; l < 2; l++) {
            int idx = tid + l * 256;
            int k = idx >> 4, c4 = idx & 15;
            *(float4*)&sW[k][c4 * 4] =
                __ldg((const float4*)(W2 + (size_t)(kc * 32 + k) * HID) + c4);
        }
        __syncthreads();

#pragma unroll
        for (int k = 0; k < 32; k++) {
            float4 w = *(const float4*)&sW[k][tx * 4];
            unsigned long long wxy = pack2(w.x, w.y);
            unsigned long long wzw = pack2(w.z, w.w);
#pragma unroll
            for (int i = 0; i < 8; i++) {
                float h = sX[ty + i * 16][k];
                unsigned long long hh = pack2(h, h);
                ffma2(axy[i], hh, wxy);
                ffma2(azw[i], hh, wzw);
            }
        }
        __syncthreads();
    }

#pragma unroll
    for (int i = 0; i < 8; i++) {
        int row = m0 + ty + i * 16;
        if (row < NNODES) {
            float dv = g_dinv[row];
            float2 pxy = unpack2(axy[i]);
            float2 pzw = unpack2(azw[i]);
            float4 v = make_float4(pxy.x * dv, pxy.y * dv, pzw.x * dv, pzw.y * dv);
            g_bufA[(size_t)row * HID4 + tx] = v;
        }
    }
}

// ---------------------------------------------------------------------------
// K6: head:  out[v] = relu(bufB[v]*dinv + b2) . Wd + bd   (warp per node)
// ---------------------------------------------------------------------------
__global__ __launch_bounds__(256) void k_final(const float* __restrict__ Wd,
                                               const float* __restrict__ b2,
                                               const float* __restrict__ bd,
                                               float* __restrict__ out) {
    int warp = (blockIdx.x * 256 + threadIdx.x) >> 5;
    int lane = threadIdx.x & 31;
    if (warp >= NNODES) return;
    float  dv = g_dinv[warp];
    float2 v  = *((const float2*)(g_bufB + (size_t)warp * HID4) + lane);
    float2 b  = __ldg((const float2*)b2 + lane);
    float2 w  = __ldg((const float2*)Wd + lane);
    float s = fmaxf(fmaf(v.x, dv, b.x), 0.f) * w.x
            + fmaxf(fmaf(v.y, dv, b.y), 0.f) * w.y;
#pragma unroll
    for (int o = 16; o > 0; o >>= 1)
        s += __shfl_down_sync(0xffffffffu, s, o);
    if (lane == 0) out[warp] = s + __ldg(bd);
}

// ---------------------------------------------------------------------------
extern "C" void kernel_launch(void* const* d_in, const int* in_sizes, int n_in,
                              void* d_out, int out_size) {
    const float* x   = (const float*)d_in[0];
    const int*   ei  = (const int*)d_in[1];     // int32 (JAX x64 disabled)
    const float* W1  = (const float*)d_in[2];
    const float* b1  = (const float*)d_in[3];
    const float* W2  = (const float*)d_in[4];
    const float* b2  = (const float*)d_in[5];
    const float* Wd  = (const float*)d_in[6];
    const float* bd  = (const float*)d_in[7];
    float*       out = (float*)d_out;

    // CSR build (once, reused by both layers)
    k_zero <<<(NNODES + 255) / 256, 256>>>();
    k_count<<<(NEDGES + 255) / 256, 256>>>(ei);
    k_scan1<<<NSCANB, SCAN_T>>>();
    k_scan2<<<1, SCAN_T>>>();
    k_scan3<<<NSCANB, SCAN_T>>>();               // + dinv fused
    k_fill <<<(NEDGES + 255) / 256, 256>>>(ei);

    // layer 1
    k_gemm1<<<(NNODES + 127) / 128, 256>>>(x, W1);
    k_aggr <<<(NNODES * 16 + 255) / 256, 256>>>();

    // layer 2
    k_layer2<<<(NNODES + 127) / 128, 256>>>(W2, b1);
    k_aggr  <<<(NNODES * 16 + 255) / 256, 256>>>();

    // head
    k_final<<<(NNODES * 32 + 255) / 256, 256>>>(Wd, b2, bd, out);
}

// round 11
// speedup vs baseline: 2.9936x; 1.0427x over previous
#include <cuda_runtime.h>
#include <cuda_bf16.h>
#include <cstdint>

// Problem constants (fixed by the dataset generator).
#define NNODES 100000
#define NEDGES 1600000
#define F_IN   128
#define HID    64
#define HID4   (HID / 4)          // float4s per node row = 16

#define SCAN_T 1024
#define NSCANB ((NNODES + SCAN_T - 1) / SCAN_T)   // 98

// Scratch (static __device__ globals -- no allocation allowed).
__device__ float  g_dinv[NNODES];
__device__ float4 g_bufA[(size_t)NNODES * HID4];   // GEMM output, gather source
__device__ float4 g_bufB[(size_t)NNODES * HID4];   // aggregated sums
__device__ int    g_degi  [NNODES];
__device__ int    g_cursor[NNODES];
__device__ int    g_rowptr[NNODES + 1];
__device__ int    g_bsum  [NSCANB];
__device__ int    g_csrc  [NEDGES];                // CSR: src ids bucketed by dst

// ---------------------------------------------------------------------------
// Packed fp32x2 helpers (Blackwell FFMA2: 2x fp32 FMA throughput, exact fp32)
// These asms only touch their explicit operands -- safe without mem clobber.
// ---------------------------------------------------------------------------
__device__ __forceinline__ unsigned long long pack2(float a, float b) {
    unsigned long long r;
    asm("mov.b64 %0, {%1, %2};" : "=l"(r) : "f"(a), "f"(b));
    return r;
}
__device__ __forceinline__ void ffma2(unsigned long long& c,
                                      unsigned long long a,
                                      unsigned long long b) {
    asm("fma.rn.f32x2 %0, %1, %2, %0;" : "+l"(c) : "l"(a), "l"(b));
}
__device__ __forceinline__ float2 unpack2(unsigned long long v) {
    float2 f;
    asm("mov.b64 {%0, %1}, %2;" : "=f"(f.x), "=f"(f.y) : "l"(v));
    return f;
}

// ---------------------------------------------------------------------------
// CSR construction
// ---------------------------------------------------------------------------
__global__ void k_zero() {
    int v = blockIdx.x * blockDim.x + threadIdx.x;
    if (v < NNODES) { g_degi[v] = 0; g_cursor[v] = 0; }
}

__global__ void k_count(const int* __restrict__ ei) {
    int e = blockIdx.x * blockDim.x + threadIdx.x;
    if (e < NEDGES) atomicAdd(&g_degi[ei[NEDGES + e]], 1);
}

// 3-phase exclusive scan of g_degi -> g_rowptr
__global__ __launch_bounds__(SCAN_T) void k_scan1() {
    __shared__ int s[SCAN_T];
    int i = blockIdx.x * SCAN_T + threadIdx.x;
    int v = (i < NNODES) ? g_degi[i] : 0;
    s[threadIdx.x] = v;
    __syncthreads();
    for (int off = 1; off < SCAN_T; off <<= 1) {
        int t = (threadIdx.x >= off) ? s[threadIdx.x - off] : 0;
        __syncthreads();
        s[threadIdx.x] += t;
        __syncthreads();
    }
    if (i < NNODES) g_rowptr[i] = s[threadIdx.x] - v;       // block-local exclusive
    if (threadIdx.x == SCAN_T - 1) g_bsum[blockIdx.x] = s[SCAN_T - 1];
}

__global__ __launch_bounds__(SCAN_T) void k_scan2() {
    __shared__ int s[SCAN_T];
    int v = (threadIdx.x < NSCANB) ? g_bsum[threadIdx.x] : 0;
    s[threadIdx.x] = v;
    __syncthreads();
    for (int off = 1; off < SCAN_T; off <<= 1) {
        int t = (threadIdx.x >= off) ? s[threadIdx.x - off] : 0;
        __syncthreads();
        s[threadIdx.x] += t;
        __syncthreads();
    }
    if (threadIdx.x < NSCANB) g_bsum[threadIdx.x] = s[threadIdx.x] - v;  // exclusive
    if (threadIdx.x == 0) g_rowptr[NNODES] = NEDGES;
}

// scan finish + dinv fused
__global__ __launch_bounds__(SCAN_T) void k_scan3() {
    int i = blockIdx.x * SCAN_T + threadIdx.x;
    if (i < NNODES) {
        g_rowptr[i] += g_bsum[blockIdx.x];
        g_dinv[i] = rsqrtf((float)(g_degi[i] + 1));
    }
}

// place each edge's src into its dst bucket
__global__ void k_fill(const int* __restrict__ ei) {
    int e = blockIdx.x * blockDim.x + threadIdx.x;
    if (e < NEDGES) {
        int s = ei[e];
        int d = ei[NEDGES + e];
        int pos = g_rowptr[d] + atomicAdd(&g_cursor[d], 1);
        g_csrc[pos] = s;
    }
}

// ---------------------------------------------------------------------------
// K3: GEMM1  bufA = (x @ W1) * dinv[row]
//   Row-pair FFMA2: sX staged k-major transposed so (row r, row r+1) sit in
//   one 8-byte word (loaded as a plain C++ u64 -> LDS.64, dependency-tracked).
//   Thread = 8 consecutive rows (4 pairs) x 4 cols.
// ---------------------------------------------------------------------------
__global__ __launch_bounds__(256) void k_gemm1(const float* __restrict__ x,
                                               const float* __restrict__ W1) {
    __shared__ __align__(16) float sXT[32][130];  // [k][row]; 520B rows (8B-aligned)
    __shared__ float sW[32][64];

    const int m0  = blockIdx.x * 128;
    const int tid = threadIdx.x;
    const int tx  = tid & 15;        // col group: cols tx*4 .. tx*4+3
    const int ty  = tid >> 4;        // row octet: rows 8*ty .. 8*ty+7

    unsigned long long acc[4][4];    // [row-pair][col]: (row even, row odd)
    const unsigned long long z2 = pack2(0.f, 0.f);
#pragma unroll
    for (int j = 0; j < 4; j++)
#pragma unroll
        for (int c = 0; c < 4; c++) acc[j][c] = z2;

#pragma unroll
    for (int kc = 0; kc < 4; kc++) {
        // stage X chunk transposed: x[row][kc*32+c] -> sXT[c][row]
#pragma unroll
        for (int l = 0; l < 4; l++) {
            int idx = tid + l * 256;          // 0..1023
            int r = idx >> 3, c4 = idx & 7;
            int row = m0 + r;
            float4 v = make_float4(0.f, 0.f, 0.f, 0.f);
            if (row < NNODES)
                v = __ldg((const float4*)(x + (size_t)row * F_IN + kc * 32) + c4);
            sXT[c4 * 4 + 0][r] = v.x;
            sXT[c4 * 4 + 1][r] = v.y;
            sXT[c4 * 4 + 2][r] = v.z;
            sXT[c4 * 4 + 3][r] = v.w;
        }
        // stage W chunk: 32 x 64
#pragma unroll
        for (int l = 0; l < 2; l++) {
            int idx = tid + l * 256;
            int k = idx >> 4, c4 = idx & 15;
            *(float4*)&sW[k][c4 * 4] =
                __ldg((const float4*)(W1 + (size_t)(kc * 32 + k) * HID) + c4);
        }
        __syncthreads();

#pragma unroll
        for (int k = 0; k < 32; k++) {
            float4 w = *(const float4*)&sW[k][tx * 4];
            unsigned long long wd[4];
            wd[0] = pack2(w.x, w.x);
            wd[1] = pack2(w.y, w.y);
            wd[2] = pack2(w.z, w.z);
            wd[3] = pack2(w.w, w.w);
#pragma unroll
            for (int j = 0; j < 4; j++) {
                unsigned long long hp =
                    *(const unsigned long long*)&sXT[k][ty * 8 + j * 2];
#pragma unroll
                for (int c = 0; c < 4; c++) ffma2(acc[j][c], hp, wd[c]);
            }
        }
        __syncthreads();
    }

#pragma unroll
    for (int j = 0; j < 4; j++) {
        int r0 = m0 + ty * 8 + j * 2;
        float2 p0 = unpack2(acc[j][0]);
        float2 p1 = unpack2(acc[j][1]);
        float2 p2 = unpack2(acc[j][2]);
        float2 p3 = unpack2(acc[j][3]);
        if (r0 < NNODES) {
            float dv = g_dinv[r0];
            g_bufA[(size_t)r0 * HID4 + tx] =
                make_float4(p0.x * dv, p1.x * dv, p2.x * dv, p3.x * dv);
        }
        if (r0 + 1 < NNODES) {
            float dv = g_dinv[r0 + 1];
            g_bufA[(size_t)(r0 + 1) * HID4 + tx] =
                make_float4(p0.y * dv, p1.y * dv, p2.y * dv, p3.y * dv);
        }
    }
}

// ---------------------------------------------------------------------------
// K4: CSR aggregation: bufB[v] = bufA[v] + sum_{s in N_in(v)} bufA[s]
// ---------------------------------------------------------------------------
__global__ __launch_bounds__(256) void k_aggr() {
    int gid = blockIdx.x * 256 + threadIdx.x;
    int v = gid >> 4;
    int q = gid & 15;
    if (v >= NNODES) return;

    float4 acc = g_bufA[(size_t)v * HID4 + q];     // self-loop term
    int beg = g_rowptr[v];
    int end = g_rowptr[v + 1];

    int i = beg;
    for (; i + 2 <= end; i += 2) {
        int s0 = g_csrc[i];
        int s1 = g_csrc[i + 1];
        float4 t0 = __ldg(g_bufA + (size_t)s0 * HID4 + q);
        float4 t1 = __ldg(g_bufA + (size_t)s1 * HID4 + q);
        acc.x += t0.x + t1.x;
        acc.y += t0.y + t1.y;
        acc.z += t0.z + t1.z;
        acc.w += t0.w + t1.w;
    }
    if (i < end) {
        int s0 = g_csrc[i];
        float4 t0 = __ldg(g_bufA + (size_t)s0 * HID4 + q);
        acc.x += t0.x; acc.y += t0.y; acc.z += t0.z; acc.w += t0.w;
    }
    g_bufB[(size_t)v * HID4 + q] = acc;
}

// ---------------------------------------------------------------------------
// K5: layer-1 finish + GEMM2 fused (row-pair FFMA2):
//   h1 = relu(bufB*dinv + b1)  staged transposed;  bufA = (h1 @ W2) * dinv
// ---------------------------------------------------------------------------
__global__ __launch_bounds__(256) void k_layer2(const float* __restrict__ W2,
                                                const float* __restrict__ b1) {
    __shared__ __align__(16) float sXT[32][130];
    __shared__ float sW[32][64];

    const int m0  = blockIdx.x * 128;
    const int tid = threadIdx.x;
    const int tx  = tid & 15;
    const int ty  = tid >> 4;

    unsigned long long acc[4][4];
    const unsigned long long z2 = pack2(0.f, 0.f);
#pragma unroll
    for (int j = 0; j < 4; j++)
#pragma unroll
        for (int c = 0; c < 4; c++) acc[j][c] = z2;

#pragma unroll
    for (int kc = 0; kc < 2; kc++) {
        // stage h1 chunk transposed with fused relu/bias/norm
#pragma unroll
        for (int l = 0; l < 4; l++) {
            int idx = tid + l * 256;
            int r = idx >> 3, c4 = idx & 7;
            int row = m0 + r;
            float4 v = make_float4(0.f, 0.f, 0.f, 0.f);
            if (row < NNODES) {
                v = g_bufB[(size_t)row * HID4 + kc * 8 + c4];
                float dv = g_dinv[row];
                float4 bb = __ldg((const float4*)b1 + kc * 8 + c4);
                v.x = fmaxf(fmaf(v.x, dv, bb.x), 0.f);
                v.y = fmaxf(fmaf(v.y, dv, bb.y), 0.f);
                v.z = fmaxf(fmaf(v.z, dv, bb.z), 0.f);
                v.w = fmaxf(fmaf(v.w, dv, bb.w), 0.f);
            }
            sXT[c4 * 4 + 0][r] = v.x;
            sXT[c4 * 4 + 1][r] = v.y;
            sXT[c4 * 4 + 2][r] = v.z;
            sXT[c4 * 4 + 3][r] = v.w;
        }
#pragma unroll
        for (int l = 0; l < 2; l++) {
            int idx = tid + l * 256;
            int k = idx >> 4, c4 = idx & 15;
            *(float4*)&sW[k][c4 * 4] =
                __ldg((const float4*)(W2 + (size_t)(kc * 32 + k) * HID) + c4);
        }
        __syncthreads();

#pragma unroll
        for (int k = 0; k < 32; k++) {
            float4 w = *(const float4*)&sW[k][tx * 4];
            unsigned long long wd[4];
            wd[0] = pack2(w.x, w.x);
            wd[1] = pack2(w.y, w.y);
            wd[2] = pack2(w.z, w.z);
            wd[3] = pack2(w.w, w.w);
#pragma unroll
            for (int j = 0; j < 4; j++) {
                unsigned long long hp =
                    *(const unsigned long long*)&sXT[k][ty * 8 + j * 2];
#pragma unroll
                for (int c = 0; c < 4; c++) ffma2(acc[j][c], hp, wd[c]);
            }
        }
        __syncthreads();
    }

#pragma unroll
    for (int j = 0; j < 4; j++) {
        int r0 = m0 + ty * 8 + j * 2;
        float2 p0 = unpack2(acc[j][0]);
        float2 p1 = unpack2(acc[j][1]);
        float2 p2 = unpack2(acc[j][2]);
        float2 p3 = unpack2(acc[j][3]);
        if (r0 < NNODES) {
            float dv = g_dinv[r0];
            g_bufA[(size_t)r0 * HID4 + tx] =
                make_float4(p0.x * dv, p1.x * dv, p2.x * dv, p3.x * dv);
        }
        if (r0 + 1 < NNODES) {
            float dv = g_dinv[r0 + 1];
            g_bufA[(size_t)(r0 + 1) * HID4 + tx] =
                make_float4(p0.y * dv, p1.y * dv, p2.y * dv, p3.y * dv);
        }
    }
}

// ---------------------------------------------------------------------------
// K6: head:  out[v] = relu(bufB[v]*dinv + b2) . Wd + bd   (warp per node)
// ---------------------------------------------------------------------------
__global__ __launch_bounds__(256) void k_final(const float* __restrict__ Wd,
                                               const float* __restrict__ b2,
                                               const float* __restrict__ bd,
                                               float* __restrict__ out) {
    int warp = (blockIdx.x * 256 + threadIdx.x) >> 5;
    int lane = threadIdx.x & 31;
    if (warp >= NNODES) return;
    float  dv = g_dinv[warp];
    float2 v  = *((const float2*)(g_bufB + (size_t)warp * HID4) + lane);
    float2 b  = __ldg((const float2*)b2 + lane);
    float2 w  = __ldg((const float2*)Wd + lane);
    float s = fmaxf(fmaf(v.x, dv, b.x), 0.f) * w.x
            + fmaxf(fmaf(v.y, dv, b.y), 0.f) * w.y;
#pragma unroll
    for (int o = 16; o > 0; o >>= 1)
        s += __shfl_down_sync(0xffffffffu, s, o);
    if (lane == 0) out[warp] = s + __ldg(bd);
}

// ---------------------------------------------------------------------------
extern "C" void kernel_launch(void* const* d_in, const int* in_sizes, int n_in,
                              void* d_out, int out_size) {
    const float* x   = (const float*)d_in[0];
    const int*   ei  = (const int*)d_in[1];     // int32 (JAX x64 disabled)
    const float* W1  = (const float*)d_in[2];
    const float* b1  = (const float*)d_in[3];
    const float* W2  = (const float*)d_in[4];
    const float* b2  = (const float*)d_in[5];
    const float* Wd  = (const float*)d_in[6];
    const float* bd  = (const float*)d_in[7];
    float*       out = (float*)d_out;

    // CSR build (once, reused by both layers)
    k_zero <<<(NNODES + 255) / 256, 256>>>();
    k_count<<<(NEDGES + 255) / 256, 256>>>(ei);
    k_scan1<<<NSCANB, SCAN_T>>>();
    k_scan2<<<1, SCAN_T>>>();
    k_scan3<<<NSCANB, SCAN_T>>>();
    k_fill <<<(NEDGES + 255) / 256, 256>>>(ei);

    // layer 1
    k_gemm1<<<(NNODES + 127) / 128, 256>>>(x, W1);
    k_aggr <<<(NNODES * 16 + 255) / 256, 256>>>();

    // layer 2
    k_layer2<<<(NNODES + 127) / 128, 256>>>(W2, b1);
    k_aggr  <<<(NNODES * 16 + 255) / 256, 256>>>();

    // head
    k_final<<<(NNODES * 32 + 255) / 256, 256>>>(Wd, b2, bd, out);
}

// round 13
// speedup vs baseline: 2.9979x; 1.0014x over previous
#include <cuda_runtime.h>
#include <cstdint>

// Problem constants (fixed by the dataset generator).
#define NNODES 100000
#define NEDGES 1600000
#define F_IN   128
#define HID    64
#define HID4   (HID / 4)          // float4s per node row = 16

#define SCAN_T 1024
#define NSCANB ((NNODES + SCAN_T - 1) / SCAN_T)   // 98

// Scratch (static __device__ globals -- no allocation allowed).
__device__ float  g_dinv[NNODES];
__device__ float4 g_bufA[(size_t)NNODES * HID4];   // GEMM output, gather source
__device__ float4 g_bufB[(size_t)NNODES * HID4];   // aggregated sums
__device__ int    g_degi  [NNODES];
__device__ int    g_cursor[NNODES];
__device__ int    g_rowptr[NNODES + 1];
__device__ int    g_bsum  [NSCANB];
__device__ int    g_csrc  [NEDGES];                // CSR: src ids bucketed by dst

// ---------------------------------------------------------------------------
// tf32 helpers (3xTF32 split: hi = rna(x), lo = x - hi, exact residual)
// ---------------------------------------------------------------------------
__device__ __forceinline__ uint32_t f2tf32(float x) {
    uint32_t r;
    asm("cvt.rna.tf32.f32 %0, %1;" : "=r"(r) : "f"(x));
    return r;
}
__device__ __forceinline__ void mma_tf32(float* d, const uint32_t* a,
                                         const uint32_t* b) {
    asm("mma.sync.aligned.m16n8k8.row.col.f32.tf32.tf32.f32 "
        "{%0,%1,%2,%3}, {%4,%5,%6,%7}, {%8,%9}, {%0,%1,%2,%3};"
        : "+f"(d[0]), "+f"(d[1]), "+f"(d[2]), "+f"(d[3])
        : "r"(a[0]), "r"(a[1]), "r"(a[2]), "r"(a[3]), "r"(b[0]), "r"(b[1]));
}
__device__ __forceinline__ void split_tf32(float x, uint32_t& hi, uint32_t& lo) {
    hi = f2tf32(x);
    lo = f2tf32(x - __uint_as_float(hi));
}

// ---------------------------------------------------------------------------
// CSR construction
// ---------------------------------------------------------------------------
__global__ void k_zero() {
    int v = blockIdx.x * blockDim.x + threadIdx.x;
    if (v < NNODES) { g_degi[v] = 0; g_cursor[v] = 0; }
}

__global__ void k_count(const int* __restrict__ ei) {
    int e = blockIdx.x * blockDim.x + threadIdx.x;
    if (e < NEDGES) atomicAdd(&g_degi[ei[NEDGES + e]], 1);
}

__global__ __launch_bounds__(SCAN_T) void k_scan1() {
    __shared__ int s[SCAN_T];
    int i = blockIdx.x * SCAN_T + threadIdx.x;
    int v = (i < NNODES) ? g_degi[i] : 0;
    s[threadIdx.x] = v;
    __syncthreads();
    for (int off = 1; off < SCAN_T; off <<= 1) {
        int t = (threadIdx.x >= off) ? s[threadIdx.x - off] : 0;
        __syncthreads();
        s[threadIdx.x] += t;
        __syncthreads();
    }
    if (i < NNODES) g_rowptr[i] = s[threadIdx.x] - v;       // block-local exclusive
    if (threadIdx.x == SCAN_T - 1) g_bsum[blockIdx.x] = s[SCAN_T - 1];
}

// scan finish (each block reduces its own prefix over 98 block sums) + dinv
__global__ __launch_bounds__(SCAN_T) void k_scan23() {
    __shared__ int sp[128];
    int t = threadIdx.x;
    if (t < 128) sp[t] = (t < blockIdx.x && t < NSCANB) ? g_bsum[t] : 0;
    __syncthreads();
    for (int off = 64; off > 0; off >>= 1) {
        if (t < off) sp[t] += sp[t + off];
        __syncthreads();
    }
    int prefix = sp[0];
    int i = blockIdx.x * SCAN_T + t;
    if (i < NNODES) {
        g_rowptr[i] += prefix;
        g_dinv[i] = rsqrtf((float)(g_degi[i] + 1));
    }
    if (blockIdx.x == 0 && t == 0) g_rowptr[NNODES] = NEDGES;
}

__global__ void k_fill(const int* __restrict__ ei) {
    int e = blockIdx.x * blockDim.x + threadIdx.x;
    if (e < NEDGES) {
        int s = ei[e];
        int d = ei[NEDGES + e];
        int pos = g_rowptr[d] + atomicAdd(&g_cursor[d], 1);
        g_csrc[pos] = s;
    }
}

// ---------------------------------------------------------------------------
// K3: GEMM1  bufA = (x @ W1) * dinv[row]   -- 3xTF32 mma.sync
//   Block tile 128x64, 8 warps (4M x 2N), warp tile 32x32 (2x4 m16n8 frags),
//   K chunked by 16 (8 chunks). hi/lo split done once at staging.
// ---------------------------------------------------------------------------
__global__ __launch_bounds__(256) void k_gemm1(const float* __restrict__ x,
                                               const float* __restrict__ W1) {
    __shared__ uint32_t sAhi[128][20], sAlo[128][20];   // [row][k], pad 20
    __shared__ uint32_t sBhi[16][72],  sBlo[16][72];    // [k][n],   pad 72

    const int m0   = blockIdx.x * 128;
    const int tid  = threadIdx.x;
    const int wid  = tid >> 5;
    const int lane = tid & 31;
    const int g    = lane >> 2;        // groupID 0..7
    const int tg   = lane & 3;         // thread-in-group 0..3
    const int wm   = (wid >> 1) * 32;  // warp M offset
    const int wn   = (wid & 1) * 32;   // warp N offset

    float acc[2][4][4];
#pragma unroll
    for (int mt = 0; mt < 2; mt++)
#pragma unroll
        for (int nt = 0; nt < 4; nt++)
#pragma unroll
            for (int c = 0; c < 4; c++) acc[mt][nt][c] = 0.f;

#pragma unroll 1
    for (int kc = 0; kc < 8; kc++) {
        // stage X chunk 128x16 with hi/lo split
#pragma unroll
        for (int l = 0; l < 2; l++) {
            int idx = tid + l * 256;           // 0..511
            int r = idx >> 2, c4 = idx & 3;
            int row = m0 + r;
            float4 v = make_float4(0.f, 0.f, 0.f, 0.f);
            if (row < NNODES)
                v = __ldg((const float4*)(x + (size_t)row * F_IN + kc * 16) + c4);
            uint4 h, lo;
            split_tf32(v.x, h.x, lo.x);
            split_tf32(v.y, h.y, lo.y);
            split_tf32(v.z, h.z, lo.z);
            split_tf32(v.w, h.w, lo.w);
            *(uint4*)&sAhi[r][c4 * 4] = h;
            *(uint4*)&sAlo[r][c4 * 4] = lo;
        }
        // stage W chunk 16x64 with hi/lo split (k-major, matches B col fragment)
        {
            int k = tid >> 4, c4 = tid & 15;   // 256 threads exactly
            float4 v = __ldg((const float4*)(W1 + (size_t)(kc * 16 + k) * HID) + c4);
            uint4 h, lo;
            split_tf32(v.x, h.x, lo.x);
            split_tf32(v.y, h.y, lo.y);
            split_tf32(v.z, h.z, lo.z);
            split_tf32(v.w, h.w, lo.w);
            *(uint4*)&sBhi[k][c4 * 4] = h;
            *(uint4*)&sBlo[k][c4 * 4] = lo;
        }
        __syncthreads();

#pragma unroll
        for (int s = 0; s < 2; s++) {
            int k0 = s * 8;
            uint32_t ahi[2][4], alo[2][4], bhi[4][2], blo[4][2];
#pragma unroll
            for (int mt = 0; mt < 2; mt++) {
                int r = wm + mt * 16 + g;
                ahi[mt][0] = sAhi[r    ][k0 + tg];
                ahi[mt][1] = sAhi[r + 8][k0 + tg];
                ahi[mt][2] = sAhi[r    ][k0 + tg + 4];
                ahi[mt][3] = sAhi[r + 8][k0 + tg + 4];
                alo[mt][0] = sAlo[r    ][k0 + tg];
                alo[mt][1] = sAlo[r + 8][k0 + tg];
                alo[mt][2] = sAlo[r    ][k0 + tg + 4];
                alo[mt][3] = sAlo[r + 8][k0 + tg + 4];
            }
#pragma unroll
            for (int nt = 0; nt < 4; nt++) {
                int n = wn + nt * 8 + g;
                bhi[nt][0] = sBhi[k0 + tg    ][n];
                bhi[nt][1] = sBhi[k0 + tg + 4][n];
                blo[nt][0] = sBlo[k0 + tg    ][n];
                blo[nt][1] = sBlo[k0 + tg + 4][n];
            }
#pragma unroll
            for (int mt = 0; mt < 2; mt++)
#pragma unroll
                for (int nt = 0; nt < 4; nt++) {
                    mma_tf32(acc[mt][nt], ahi[mt], bhi[nt]);
                    mma_tf32(acc[mt][nt], ahi[mt], blo[nt]);
                    mma_tf32(acc[mt][nt], alo[mt], bhi[nt]);
                }
        }
        __syncthreads();
    }

    // epilogue: scale by dinv, store float2 pairs (c0,c1)/(c2,c3)
    float2* outp = (float2*)g_bufA;
#pragma unroll
    for (int mt = 0; mt < 2; mt++) {
        int r0 = m0 + wm + mt * 16 + g;
        int r1 = r0 + 8;
        float dv0 = (r0 < NNODES) ? g_dinv[r0] : 0.f;
        float dv1 = (r1 < NNODES) ? g_dinv[r1] : 0.f;
#pragma unroll
        for (int nt = 0; nt < 4; nt++) {
            int c2 = (wn + nt * 8) / 2 + tg;
            if (r0 < NNODES)
                outp[(size_t)r0 * 32 + c2] =
                    make_float2(acc[mt][nt][0] * dv0, acc[mt][nt][1] * dv0);
            if (r1 < NNODES)
                outp[(size_t)r1 * 32 + c2] =
                    make_float2(acc[mt][nt][2] * dv1, acc[mt][nt][3] * dv1);
        }
    }
}

// ---------------------------------------------------------------------------
// K4: CSR aggregation: bufB[v] = bufA[v] + sum_{s in N_in(v)} bufA[s]
// ---------------------------------------------------------------------------
__global__ __launch_bounds__(256) void k_aggr() {
    int gid = blockIdx.x * 256 + threadIdx.x;
    int v = gid >> 4;
    int q = gid & 15;
    if (v >= NNODES) return;

    float4 acc = g_bufA[(size_t)v * HID4 + q];     // self-loop term
    int beg = g_rowptr[v];
    int end = g_rowptr[v + 1];

    int i = beg;
    for (; i + 2 <= end; i += 2) {
        int s0 = g_csrc[i];
        int s1 = g_csrc[i + 1];
        float4 t0 = __ldg(g_bufA + (size_t)s0 * HID4 + q);
        float4 t1 = __ldg(g_bufA + (size_t)s1 * HID4 + q);
        acc.x += t0.x + t1.x;
        acc.y += t0.y + t1.y;
        acc.z += t0.z + t1.z;
        acc.w += t0.w + t1.w;
    }
    if (i < end) {
        int s0 = g_csrc[i];
        float4 t0 = __ldg(g_bufA + (size_t)s0 * HID4 + q);
        acc.x += t0.x; acc.y += t0.y; acc.z += t0.z; acc.w += t0.w;
    }
    g_bufB[(size_t)v * HID4 + q] = acc;
}

// ---------------------------------------------------------------------------
// K5: layer-1 finish + GEMM2 fused (3xTF32):
//   h1 = relu(bufB*dinv + b1) staged with hi/lo split; bufA = (h1 @ W2)*dinv
// ---------------------------------------------------------------------------
__global__ __launch_bounds__(256) void k_layer2(const float* __restrict__ W2,
                                                const float* __restrict__ b1) {
    __shared__ uint32_t sAhi[128][20], sAlo[128][20];
    __shared__ uint32_t sBhi[16][72],  sBlo[16][72];

    const int m0   = blockIdx.x * 128;
    const int tid  = threadIdx.x;
    const int wid  = tid >> 5;
    const int lane = tid & 31;
    const int g    = lane >> 2;
    const int tg   = lane & 3;
    const int wm   = (wid >> 1) * 32;
    const int wn   = (wid & 1) * 32;

    float acc[2][4][4];
#pragma unroll
    for (int mt = 0; mt < 2; mt++)
#pragma unroll
        for (int nt = 0; nt < 4; nt++)
#pragma unroll
            for (int c = 0; c < 4; c++) acc[mt][nt][c] = 0.f;

#pragma unroll 1
    for (int kc = 0; kc < 4; kc++) {
        // stage h1 chunk 128x16 with fused relu/bias/norm + hi/lo split
#pragma unroll
        for (int l = 0; l < 2; l++) {
            int idx = tid + l * 256;
            int r = idx >> 2, c4 = idx & 3;
            int row = m0 + r;
            float4 v = make_float4(0.f, 0.f, 0.f, 0.f);
            if (row < NNODES) {
                v = g_bufB[(size_t)row * HID4 + kc * 4 + c4];
                float dv = g_dinv[row];
                float4 bb = __ldg((const float4*)b1 + kc * 4 + c4);
                v.x = fmaxf(fmaf(v.x, dv, bb.x), 0.f);
                v.y = fmaxf(fmaf(v.y, dv, bb.y), 0.f);
                v.z = fmaxf(fmaf(v.z, dv, bb.z), 0.f);
                v.w = fmaxf(fmaf(v.w, dv, bb.w), 0.f);
            }
            uint4 h, lo;
            split_tf32(v.x, h.x, lo.x);
            split_tf32(v.y, h.y, lo.y);
            split_tf32(v.z, h.z, lo.z);
            split_tf32(v.w, h.w, lo.w);
            *(uint4*)&sAhi[r][c4 * 4] = h;
            *(uint4*)&sAlo[r][c4 * 4] = lo;
        }
        {
            int k = tid >> 4, c4 = tid & 15;
            float4 v = __ldg((const float4*)(W2 + (size_t)(kc * 16 + k) * HID) + c4);
            uint4 h, lo;
            split_tf32(v.x, h.x, lo.x);
            split_tf32(v.y, h.y, lo.y);
            split_tf32(v.z, h.z, lo.z);
            split_tf32(v.w, h.w, lo.w);
            *(uint4*)&sBhi[k][c4 * 4] = h;
            *(uint4*)&sBlo[k][c4 * 4] = lo;
        }
        __syncthreads();

#pragma unroll
        for (int s = 0; s < 2; s++) {
            int k0 = s * 8;
            uint32_t ahi[2][4], alo[2][4], bhi[4][2], blo[4][2];
#pragma unroll
            for (int mt = 0; mt < 2; mt++) {
                int r = wm + mt * 16 + g;
                ahi[mt][0] = sAhi[r    ][k0 + tg];
                ahi[mt][1] = sAhi[r + 8][k0 + tg];
                ahi[mt][2] = sAhi[r    ][k0 + tg + 4];
                ahi[mt][3] = sAhi[r + 8][k0 + tg + 4];
                alo[mt][0] = sAlo[r    ][k0 + tg];
                alo[mt][1] = sAlo[r + 8][k0 + tg];
                alo[mt][2] = sAlo[r    ][k0 + tg + 4];
                alo[mt][3] = sAlo[r + 8][k0 + tg + 4];
            }
#pragma unroll
            for (int nt = 0; nt < 4; nt++) {
                int n = wn + nt * 8 + g;
                bhi[nt][0] = sBhi[k0 + tg    ][n];
                bhi[nt][1] = sBhi[k0 + tg + 4][n];
                blo[nt][0] = sBlo[k0 + tg    ][n];
                blo[nt][1] = sBlo[k0 + tg + 4][n];
            }
#pragma unroll
            for (int mt = 0; mt < 2; mt++)
#pragma unroll
                for (int nt = 0; nt < 4; nt++) {
                    mma_tf32(acc[mt][nt], ahi[mt], bhi[nt]);
                    mma_tf32(acc[mt][nt], ahi[mt], blo[nt]);
                    mma_tf32(acc[mt][nt], alo[mt], bhi[nt]);
                }
        }
        __syncthreads();
    }

    float2* outp = (float2*)g_bufA;
#pragma unroll
    for (int mt = 0; mt < 2; mt++) {
        int r0 = m0 + wm + mt * 16 + g;
        int r1 = r0 + 8;
        float dv0 = (r0 < NNODES) ? g_dinv[r0] : 0.f;
        float dv1 = (r1 < NNODES) ? g_dinv[r1] : 0.f;
#pragma unroll
        for (int nt = 0; nt < 4; nt++) {
            int c2 = (wn + nt * 8) / 2 + tg;
            if (r0 < NNODES)
                outp[(size_t)r0 * 32 + c2] =
                    make_float2(acc[mt][nt][0] * dv0, acc[mt][nt][1] * dv0);
            if (r1 < NNODES)
                outp[(size_t)r1 * 32 + c2] =
                    make_float2(acc[mt][nt][2] * dv1, acc[mt][nt][3] * dv1);
        }
    }
}

// ---------------------------------------------------------------------------
// K6: head:  out[v] = relu(bufB[v]*dinv + b2) . Wd + bd   (warp per node)
// ---------------------------------------------------------------------------
__global__ __launch_bounds__(256) void k_final(const float* __restrict__ Wd,
                                               const float* __restrict__ b2,
                                               const float* __restrict__ bd,
                                               float* __restrict__ out) {
    int warp = (blockIdx.x * 256 + threadIdx.x) >> 5;
    int lane = threadIdx.x & 31;
    if (warp >= NNODES) return;
    float  dv = g_dinv[warp];
    float2 v  = *((const float2*)(g_bufB + (size_t)warp * HID4) + lane);
    float2 b  = __ldg((const float2*)b2 + lane);
    float2 w  = __ldg((const float2*)Wd + lane);
    float s = fmaxf(fmaf(v.x, dv, b.x), 0.f) * w.x
            + fmaxf(fmaf(v.y, dv, b.y), 0.f) * w.y;
#pragma unroll
    for (int o = 16; o > 0; o >>= 1)
        s += __shfl_down_sync(0xffffffffu, s, o);
    if (lane == 0) out[warp] = s + __ldg(bd);
}

// ---------------------------------------------------------------------------
extern "C" void kernel_launch(void* const* d_in, const int* in_sizes, int n_in,
                              void* d_out, int out_size) {
    const float* x   = (const float*)d_in[0];
    const int*   ei  = (const int*)d_in[1];     // int32 (JAX x64 disabled)
    const float* W1  = (const float*)d_in[2];
    const float* b1  = (const float*)d_in[3];
    const float* W2  = (const float*)d_in[4];
    const float* b2  = (const float*)d_in[5];
    const float* Wd  = (const float*)d_in[6];
    const float* bd  = (const float*)d_in[7];
    float*       out = (float*)d_out;

    // CSR build (once, reused by both layers)
    k_zero  <<<(NNODES + 255) / 256, 256>>>();
    k_count <<<(NEDGES + 255) / 256, 256>>>(ei);
    k_scan1 <<<NSCANB, SCAN_T>>>();
    k_scan23<<<NSCANB, SCAN_T>>>();
    k_fill  <<<(NEDGES + 255) / 256, 256>>>(ei);

    // layer 1
    k_gemm1<<<(NNODES + 127) / 128, 256>>>(x, W1);
    k_aggr <<<(NNODES * 16 + 255) / 256, 256>>>();

    // layer 2
    k_layer2<<<(NNODES + 127) / 128, 256>>>(W2, b1);
    k_aggr  <<<(NNODES * 16 + 255) / 256, 256>>>();

    // head
    k_final<<<(NNODES * 32 + 255) / 256, 256>>>(Wd, b2, bd, out);
}